// round 16
// baseline (speedup 1.0000x reference)
#include <cuda_runtime.h>
#include <math.h>

// Problem constants
#define BB 32
#define LL 2880
#define CC 862
#define PREDP 720
#define SEGS 48
#define KK 16
#define NINV 60
#define NOUTV 15
#define CDIMV 359
#define NMM 4

#define CPB 4
#define XROW 2884            // padded smem row stride (floats), %32 == 4
#define CBLKS 216            // ceil(862/4)
#define UNITS (BB * CBLKS)   // 6912
#define NTHR 512             // 256 consumers + 256 loaders

// smem float offsets (per CTA; 114,032 B -> 2 CTAs/SM -> 32 warps/SM)
#define O_XS0   0
#define O_XS1   11536
#define O_SMW   23072        // 3600: map_w transposed [i*60 + o*4 + m]
#define O_GWU   26672        // 1436: gate_w (staged once; never overwritten)
#define O_SCRC  28108        // 128 : consumer reduction scratch (8 warps x 16)
#define O_SCRL  28236        // 128 : loader stats scratch (2 bufs x 64)
#define O_GTS   28364        // 16  : gates [4][4]
#define O_STAT  28380        // 64  : per-buf {mean[4]@0, sd[4]@8, istd[4]@16}
#define O_SMB   28444        // 64  : map_b transposed [o*4+m], zero-padded
#define SMEM_FLOATS 28508    // 114,032 bytes

// named barrier ids
#define BFULL0  1            // +buf  (512)
#define BEMPTY0 3            // +buf  (512)
#define BLSYNC  5            // loader-internal (256)
#define BCSYNC  6            // consumer-internal (256)

__device__ __forceinline__ void bar_sync(int id, int cnt) {
    asm volatile("bar.sync %0, %1;" :: "r"(id), "r"(cnt) : "memory");
}
__device__ __forceinline__ void bar_arrive(int id, int cnt) {
    asm volatile("bar.arrive %0, %1;" :: "r"(id), "r"(cnt) : "memory");
}

__global__ __launch_bounds__(NTHR, 2)
void fused_model_kernel(const float* __restrict__ x,
                        const float* __restrict__ conv_w,
                        const float* __restrict__ conv_b,
                        const float* __restrict__ gate_w,
                        const float* __restrict__ gate_b,
                        const float* __restrict__ map_w,
                        const float* __restrict__ map_b,
                        float* __restrict__ out,
                        int gridn)
{
    extern __shared__ float sm[];
    float* smw   = sm + O_SMW;
    float* gwu   = sm + O_GWU;
    float* scrC  = sm + O_SCRC;
    float* scrL  = sm + O_SCRL;
    float* gts   = sm + O_GTS;
    float* statv = sm + O_STAT;
    float* smb   = sm + O_SMB;

    const int t   = threadIdx.x;
    const int bid = blockIdx.x;
    const int nu  = (bid < UNITS) ? ((UNITS - 1 - bid) / gridn + 1) : 0;

    // ---- one-time staging ----
    for (int q = t; q < 900; q += NTHR) {
        int m = q / 225, r = q % 225;
        int o_ = r / 15, i4 = (r % 15) * 4;
        float4 v = *(const float4*)(map_w + m * 900 + o_ * 60 + i4);
        smw[(i4 + 0) * 60 + o_ * 4 + m] = v.x;
        smw[(i4 + 1) * 60 + o_ * 4 + m] = v.y;
        smw[(i4 + 2) * 60 + o_ * 4 + m] = v.z;
        smw[(i4 + 3) * 60 + o_ * 4 + m] = v.w;
    }
    for (int i = t; i < NMM * CDIMV; i += NTHR)
        gwu[i] = __ldg(gate_w + i);
    if (t < 64) {
        int o = t >> 2, m = t & 3;
        smb[t] = (o < NOUTV) ? __ldg(map_b + m * NOUTV + o) : 0.f;
    }
    __syncthreads();
    if (nu == 0) return;

    if (t >= 256) {
        // ==================== LOADER role (warps 8-15, 256 threads) =========
        const int tl   = t - 256;
        const int pr   = tl & 1;            // channel pair 0..1
        const int lane = tl >> 1;           // 0..127
        const int w    = tl >> 5;           // loader warp 0..7

        for (int k = 0; k < nu + 2; k++) {
            const int buf = k & 1;
            float* xb = sm + (buf ? O_XS1 : O_XS0);

            if (k >= 2) {
                bar_sync(BEMPTY0 + buf, NTHR);   // consumer staged k-2's output
                const int uo  = bid + (k - 2) * gridn;
                const int bo  = uo / CBLKS;
                const int co0 = (uo % CBLKS) * CPB;
                const size_t obase = (size_t)bo * PREDP * CC + co0;
                for (int idx = tl; idx < 2 * PREDP; idx += 256) {
                    int pr2 = idx & 1, p = idx >> 1;
                    int c = co0 + pr2 * 2;
                    float2 v;
                    v.x = xb[(pr2 * 2) * XROW + p];
                    v.y = xb[(pr2 * 2 + 1) * XROW + p];
                    if (c + 1 < CC)
                        *(float2*)(out + obase + (size_t)p * CC + pr2 * 2) = v;
                    else if (c < CC)
                        out[obase + (size_t)p * CC + pr2 * 2] = v.x;
                }
                bar_sync(BLSYNC, 256);   // writeout reads done before gather
            }
            if (k >= nu) continue;        // tail: writeout only

            // ---- gather unit k (float2, 128 lanes, stride 128, unroll 5) ----
            const int u = bid + k * gridn;
            const int b = u / CBLKS;
            const int c = (u % CBLKS) * CPB + pr * 2;
            const bool v0 = (c < CC), v1 = (c + 1 < CC);
            const float* gp = x + (size_t)b * LL * CC + c;
            float* r0 = xb + (pr * 2) * XROW;
            float* r1 = r0 + XROW;
            float s0 = 0.f, q0 = 0.f, s1 = 0.f, q1 = 0.f;
            if (v1) {
                #pragma unroll 5
                for (int l = lane; l < LL; l += 128) {
                    float2 vv = *(const float2*)(gp + (size_t)l * CC);
                    r0[l] = vv.x; r1[l] = vv.y;
                    s0 += vv.x; q0 = fmaf(vv.x, vv.x, q0);
                    s1 += vv.y; q1 = fmaf(vv.y, vv.y, q1);
                }
            } else {
                for (int l = lane; l < LL; l += 128) {
                    float a = v0 ? __ldg(gp + (size_t)l * CC) : 0.f;
                    r0[l] = a; r1[l] = 0.f;
                    s0 += a; q0 = fmaf(a, a, q0);
                }
            }
            // reduce over same-pair lanes within warp (tl stride 2)
            #pragma unroll
            for (int off = 2; off <= 16; off <<= 1) {
                s0 += __shfl_xor_sync(0xffffffffu, s0, off);
                s1 += __shfl_xor_sync(0xffffffffu, s1, off);
                q0 += __shfl_xor_sync(0xffffffffu, q0, off);
                q1 += __shfl_xor_sync(0xffffffffu, q1, off);
            }
            if ((tl & 31) < 2) {
                float* p = scrL + buf * 64 + w * 8 + pr * 4;
                p[0] = s0; p[1] = s1; p[2] = q0; p[3] = q1;
            }
            bar_sync(BLSYNC, 256);
            if (tl < 4) {          // tl = channel 0..3
                int pp = tl >> 1, e = tl & 1;
                float s = 0.f, qq = 0.f;
                #pragma unroll
                for (int ww = 0; ww < 8; ww++) {
                    s  += scrL[buf * 64 + ww * 8 + pp * 4 + e];
                    qq += scrL[buf * 64 + ww * 8 + pp * 4 + 2 + e];
                }
                float mean = s * (1.f / LL);
                float var  = fmaxf(qq * (1.f / LL) - mean * mean, 0.f);
                float sd   = sqrtf(var + 1e-10f);
                float* st = statv + buf * 32;
                st[tl] = mean; st[8 + tl] = sd; st[16 + tl] = 1.f / sd;
            }
            bar_arrive(BFULL0 + buf, NTHR);
        }
    } else {
        // ==================== CONSUMER role (warps 0-7, 256 threads) ========
        const int ch = t & 3;               // conv channel 0..3
        const int dl = t >> 2;              // conv d-lane 0..63 (6 d's each)
        // matmul mapping (t < 240): pch = t/60, po = (t%60)>>2, pq = t&3
        const bool mact = (t < 240);
        const int pch = t / 60;
        const int prem = t % 60;
        const int po = prem >> 2;           // 0..14
        const int pq = prem & 3;            // quarter of 12 preds

        for (int k = 0; k < nu; k++) {
            const int u   = bid + k * gridn;
            const int buf = k & 1;
            float* xb = sm + (buf ? O_XS1 : O_XS0);
            const float* st = statv + buf * 32;
            const int c0 = (u % CBLKS) * CPB;

            // prefetch conv weights before waiting on FULL
            float4 kA, kB, kC, kD; float cb;
            {
                int c = c0 + ch;
                if (c < CC) {
                    const float4* cwp = (const float4*)(conv_w + c * KK);
                    kA = cwp[0]; kB = cwp[1]; kC = cwp[2]; kD = cwp[3];
                    cb = __ldg(conv_b + c);
                } else {
                    kA = make_float4(0.f,0.f,0.f,0.f);
                    kB = kA; kC = kA; kD = kA; cb = 0.f;
                }
            }
            bar_sync(BFULL0 + buf, NTHR);

            // ---- depthwise conv on RAW x (normalize folded) + gate partials ----
            {
                const float ksum = kA.x+kA.y+kA.z+kA.w + kB.x+kB.y+kB.z+kB.w
                                 + kC.x+kC.y+kC.z+kC.w + kD.x+kD.y+kD.z+kD.w;
                const float scale  = st[16 + ch];
                const float offset = cb - st[ch] * ksum * scale;
                const float* row = xb + ch * XROW;
                const int d0 = dl * 6;
                const int dend = (d0 + 6 < CDIMV) ? d0 + 6 : CDIMV;
                float a0 = 0.f, a1 = 0.f, a2 = 0.f, a3 = 0.f;
                if (d0 < dend) {
                    const float4* base = (const float4*)(row + 8 * d0);
                    float4 w0 = base[0], w1 = base[1], w2 = base[2], w3 = base[3];
                    for (int d = d0; d < dend; d++) {
                        float dot = 0.f;
                        dot = fmaf(w0.x, kA.x, dot); dot = fmaf(w0.y, kA.y, dot);
                        dot = fmaf(w0.z, kA.z, dot); dot = fmaf(w0.w, kA.w, dot);
                        dot = fmaf(w1.x, kB.x, dot); dot = fmaf(w1.y, kB.y, dot);
                        dot = fmaf(w1.z, kB.z, dot); dot = fmaf(w1.w, kB.w, dot);
                        dot = fmaf(w2.x, kC.x, dot); dot = fmaf(w2.y, kC.y, dot);
                        dot = fmaf(w2.z, kC.z, dot); dot = fmaf(w2.w, kC.w, dot);
                        dot = fmaf(w3.x, kD.x, dot); dot = fmaf(w3.y, kD.y, dot);
                        dot = fmaf(w3.z, kD.z, dot); dot = fmaf(w3.w, kD.w, dot);
                        float cv = fmaf(dot, scale, offset);
                        int j = d - d0;
                        if (d + 1 < dend) {
                            w0 = w2; w1 = w3;
                            w2 = base[2 * j + 4];
                            w3 = base[2 * j + 5];
                        }
                        a0 = fmaf(cv, gwu[d],             a0);
                        a1 = fmaf(cv, gwu[CDIMV + d],     a1);
                        a2 = fmaf(cv, gwu[2 * CDIMV + d], a2);
                        a3 = fmaf(cv, gwu[3 * CDIMV + d], a3);
                    }
                }
                // reduce over same-ch lanes within warp (t stride 4)
                #pragma unroll
                for (int off = 4; off <= 16; off <<= 1) {
                    a0 += __shfl_xor_sync(0xffffffffu, a0, off);
                    a1 += __shfl_xor_sync(0xffffffffu, a1, off);
                    a2 += __shfl_xor_sync(0xffffffffu, a2, off);
                    a3 += __shfl_xor_sync(0xffffffffu, a3, off);
                }
                if ((t & 31) < 4) {
                    int w = t >> 5;
                    float* p = scrC + w * 16 + ch * 4;
                    p[0] = a0; p[1] = a1; p[2] = a2; p[3] = a3;
                }
            }
            bar_sync(BCSYNC, 256);
            if (t < 16) {
                int cc = t >> 2, m = t & 3;
                float s = 0.f;
                #pragma unroll
                for (int w = 0; w < 8; w++) s += scrC[w * 16 + cc * 4 + m];
                gts[cc * 4 + m] = s + __ldg(gate_b + m);
            }
            __syncwarp();
            if (t < CPB) {
                float g0 = gts[t*4], g1 = gts[t*4+1], g2 = gts[t*4+2], g3 = gts[t*4+3];
                float mx = fmaxf(fmaxf(g0, g1), fmaxf(g2, g3));
                g0 = expf(g0-mx); g1 = expf(g1-mx); g2 = expf(g2-mx); g3 = expf(g3-mx);
                float inv = 1.f / (g0 + g1 + g2 + g3);
                gts[t*4] = g0*inv; gts[t*4+1] = g1*inv;
                gts[t*4+2] = g2*inv; gts[t*4+3] = g3*inv;
            }
            bar_sync(BCSYNC, 256);

            // ---- map matmul: thread=(ch,o,quarter), gates folded on the fly ----
            unsigned long long acc[6];
            float bf = 0.f;
            if (mact) {
                const float4 g = *(const float4*)(gts + pch * 4);
                const float* row = xb + pch * XROW + pq * 12;
                const float* mwp = smw + po * 4;
                #pragma unroll
                for (int s = 0; s < 6; s++) acc[s] = 0ULL;
                float rw = 0.f;
                #pragma unroll 4
                for (int i = 0; i < NINV; i++) {
                    float4 mw = *(const float4*)(mwp + i * 60);
                    float w = g.x * mw.x;
                    w = fmaf(g.y, mw.y, w);
                    w = fmaf(g.z, mw.z, w);
                    w = fmaf(g.w, mw.w, w);
                    rw += w;
                    unsigned long long w2;
                    asm("mov.b64 %0, {%1, %1};" : "=l"(w2) : "f"(w));
                    const float* xp = row + i * SEGS;
                    #pragma unroll
                    for (int s = 0; s < 3; s++) {
                        unsigned long long xl = *(const unsigned long long*)(xp + s * 4);
                        unsigned long long xh = *(const unsigned long long*)(xp + s * 4 + 2);
                        asm("fma.rn.f32x2 %0, %1, %2, %0;" : "+l"(acc[2*s])   : "l"(w2), "l"(xl));
                        asm("fma.rn.f32x2 %0, %1, %2, %0;" : "+l"(acc[2*s+1]) : "l"(w2), "l"(xh));
                    }
                }
                float4 mb4 = *(const float4*)(smb + po * 4);
                float be = g.x*mb4.x + g.y*mb4.y + g.z*mb4.z + g.w*mb4.w;
                bf = be * st[8 + pch] + st[pch] * (1.f - rw);
            }
            bar_sync(BCSYNC, 256);   // all x reads done before staging overwrites xb
            if (mact) {
                float* op = xb + pch * XROW + po * SEGS + pq * 12;
                #pragma unroll
                for (int s = 0; s < 3; s++) {
                    float l0, h0, l1, h1;
                    asm("mov.b64 {%0, %1}, %2;" : "=f"(l0), "=f"(h0) : "l"(acc[2*s]));
                    asm("mov.b64 {%0, %1}, %2;" : "=f"(l1), "=f"(h1) : "l"(acc[2*s+1]));
                    float4 r = make_float4(l0 + bf, h0 + bf, l1 + bf, h1 + bf);
                    *(float4*)(op + s * 4) = r;
                }
            }
            bar_arrive(BEMPTY0 + buf, NTHR);   // loader writes this buffer out
        }
    }
}

extern "C" void kernel_launch(void* const* d_in, const int* in_sizes, int n_in,
                              void* d_out, int out_size)
{
    const float* x      = (const float*)d_in[0];
    const float* conv_w = (const float*)d_in[1];
    const float* conv_b = (const float*)d_in[2];
    const float* gate_w = (const float*)d_in[3];
    const float* gate_b = (const float*)d_in[4];
    const float* map_w  = (const float*)d_in[5];
    const float* map_b  = (const float*)d_in[6];
    float* out = (float*)d_out;

    int dev = 0, nsm = 148;
    cudaGetDevice(&dev);
    cudaDeviceGetAttribute(&nsm, cudaDevAttrMultiProcessorCount, dev);
    int grid = 2 * nsm;                  // 2 CTAs per SM, 32 warps/SM
    if (grid > UNITS) grid = UNITS;

    const int smem_bytes = SMEM_FLOATS * (int)sizeof(float);   // 114,032 B
    cudaFuncSetAttribute(fused_model_kernel,
                         cudaFuncAttributeMaxDynamicSharedMemorySize, smem_bytes);

    fused_model_kernel<<<grid, NTHR, smem_bytes>>>(x, conv_w, conv_b, gate_w,
                                                   gate_b, map_w, map_b, out, grid);
}

// round 17
// speedup vs baseline: 1.9681x; 1.9681x over previous
#include <cuda_runtime.h>
#include <math.h>

// Problem constants
#define BB 32
#define LL 2880
#define CC 862
#define CPAD 864
#define PREDP 720
#define SEGS 48
#define KK 16
#define NINV 60
#define NOUTV 15
#define CDIMV 359
#define NMM 4
#define NCHUNK 8

// scratch
__device__ float g_part[BB * NCHUNK * 6 * CPAD];   // [b][chunk][e][c] e={s,s2,A0..A3}
__device__ float g_stat[BB * 6 * CPAD];            // [b][e][c] e={g0..g3,mean,sd}

// ============ Kernel A: fused stats + depthwise conv + gate partials ==========
// thread = (b, chunk, c). One streaming pass over 360(+8) rows, rolling window.
__global__ __launch_bounds__(256)
void kA_stats_conv(const float* __restrict__ x,
                   const float* __restrict__ conv_w,
                   const float* __restrict__ gate_w)
{
    __shared__ float gws[CDIMV * 4];     // gate_w transposed [d*4+m]
    const int tid = threadIdx.x;
    const int bx  = blockIdx.x;
    const int ctile = bx & 3, chunk = (bx >> 2) & 7, b = bx >> 5;

    for (int i = tid; i < CDIMV * 4; i += 256) {
        int d = i >> 2, m = i & 3;
        gws[i] = __ldg(gate_w + m * CDIMV + d);
    }
    __syncthreads();

    const int c = ctile * 256 + tid;
    const bool valid = (c < CC);
    const int cs = valid ? c : 0;
    const float* xp = x + ((size_t)b * LL + chunk * 360) * CC + cs;

    float cw[16];
    #pragma unroll
    for (int kk = 0; kk < KK; kk++)
        cw[kk] = valid ? __ldg(conv_w + cs * KK + kk) : 0.f;

    float prev[8];
    float s = 0.f, s2 = 0.f;
    #pragma unroll
    for (int j = 0; j < 8; j++) {
        float v = valid ? __ldg(xp + (size_t)j * CC) : 0.f;
        prev[j] = v; s += v; s2 = fmaf(v, v, s2);
    }
    float A0 = 0.f, A1 = 0.f, A2 = 0.f, A3 = 0.f;
    const int dbase = chunk * 45;
    const int nd = (dbase + 45 <= CDIMV) ? 45 : (CDIMV - dbase);

    for (int blk = 0; blk < nd; blk++) {
        float cur[8];
        const float* cp = xp + (size_t)(8 * blk + 8) * CC;
        #pragma unroll
        for (int j = 0; j < 8; j++)
            cur[j] = valid ? __ldg(cp + (size_t)j * CC) : 0.f;
        if (blk < 44) {                      // stats cover exactly 360 rows
            #pragma unroll
            for (int j = 0; j < 8; j++) { s += cur[j]; s2 = fmaf(cur[j], cur[j], s2); }
        }
        float dot = 0.f;
        #pragma unroll
        for (int j = 0; j < 8; j++) dot = fmaf(prev[j], cw[j], dot);
        #pragma unroll
        for (int j = 0; j < 8; j++) dot = fmaf(cur[j], cw[8 + j], dot);
        float4 gv = *(const float4*)(gws + (dbase + blk) * 4);
        A0 = fmaf(dot, gv.x, A0); A1 = fmaf(dot, gv.y, A1);
        A2 = fmaf(dot, gv.z, A2); A3 = fmaf(dot, gv.w, A3);
        #pragma unroll
        for (int j = 0; j < 8; j++) prev[j] = cur[j];
    }
    if (valid) {
        float* pp = g_part + (size_t)(b * NCHUNK + chunk) * 6 * CPAD + c;
        pp[0]        = s;  pp[CPAD]     = s2;
        pp[2 * CPAD] = A0; pp[3 * CPAD] = A1;
        pp[4 * CPAD] = A2; pp[5 * CPAD] = A3;
    }
}

// ============ Kernel B: reduce chunks -> stats + softmax gates ================
__global__ __launch_bounds__(256)
void kB_gates(const float* __restrict__ conv_w,
              const float* __restrict__ conv_b,
              const float* __restrict__ gate_w,
              const float* __restrict__ gate_b)
{
    __shared__ float gred[4][8];
    __shared__ float G4[4];
    const int tid = threadIdx.x;
    const int bx  = blockIdx.x;
    const int ctile = bx & 3, b = bx >> 2;

    // block-wide G_m = sum_d gate_w[m][d]
    {
        float g[4] = {0.f, 0.f, 0.f, 0.f};
        for (int d = tid; d < CDIMV; d += 256) {
            g[0] += __ldg(gate_w + d);
            g[1] += __ldg(gate_w + CDIMV + d);
            g[2] += __ldg(gate_w + 2 * CDIMV + d);
            g[3] += __ldg(gate_w + 3 * CDIMV + d);
        }
        #pragma unroll
        for (int off = 16; off; off >>= 1) {
            #pragma unroll
            for (int m = 0; m < 4; m++)
                g[m] += __shfl_down_sync(0xffffffffu, g[m], off);
        }
        if ((tid & 31) == 0) {
            int w = tid >> 5;
            #pragma unroll
            for (int m = 0; m < 4; m++) gred[m][w] = g[m];
        }
        __syncthreads();
        if (tid < 4) {
            float sum = 0.f;
            #pragma unroll
            for (int w = 0; w < 8; w++) sum += gred[tid][w];
            G4[tid] = sum;
        }
        __syncthreads();
    }

    const int c = ctile * 256 + tid;
    if (c >= CC) return;

    float s = 0.f, s2 = 0.f, A0 = 0.f, A1 = 0.f, A2 = 0.f, A3 = 0.f;
    #pragma unroll
    for (int ch = 0; ch < NCHUNK; ch++) {
        const float* pp = g_part + (size_t)(b * NCHUNK + ch) * 6 * CPAD + c;
        s  += pp[0];        s2 += pp[CPAD];
        A0 += pp[2 * CPAD]; A1 += pp[3 * CPAD];
        A2 += pp[4 * CPAD]; A3 += pp[5 * CPAD];
    }
    float mean = s * (1.f / LL);
    float var  = fmaxf(s2 * (1.f / LL) - mean * mean, 0.f);
    float sd   = sqrtf(var + 1e-10f);
    float istd = 1.f / sd;

    float ksum = 0.f;
    #pragma unroll
    for (int kk = 0; kk < KK; kk++) ksum += __ldg(conv_w + c * KK + kk);
    float offset = __ldg(conv_b + c) - mean * ksum * istd;

    float l0 = istd * A0 + offset * G4[0] + __ldg(gate_b + 0);
    float l1 = istd * A1 + offset * G4[1] + __ldg(gate_b + 1);
    float l2 = istd * A2 + offset * G4[2] + __ldg(gate_b + 2);
    float l3 = istd * A3 + offset * G4[3] + __ldg(gate_b + 3);
    float mx = fmaxf(fmaxf(l0, l1), fmaxf(l2, l3));
    l0 = expf(l0 - mx); l1 = expf(l1 - mx); l2 = expf(l2 - mx); l3 = expf(l3 - mx);
    float inv = 1.f / (l0 + l1 + l2 + l3);

    float* sp = g_stat + (size_t)b * 6 * CPAD + c;
    sp[0]        = l0 * inv; sp[CPAD]     = l1 * inv;
    sp[2 * CPAD] = l2 * inv; sp[3 * CPAD] = l3 * inv;
    sp[4 * CPAD] = mean;     sp[5 * CPAD] = sd;
}

// ============ Kernel C: gated map matmul + denorm + output ====================
// thread = (b, c, 6-pred block). Gates folded on the fly; 90 fp32 accumulators.
__global__ __launch_bounds__(256)
void kC_map(const float* __restrict__ x,
            const float* __restrict__ map_w,
            const float* __restrict__ map_b,
            float* __restrict__ out)
{
    __shared__ float smw[3600];          // map_w transposed [i*60 + o*4 + m]
    const int tid = threadIdx.x;
    const int bx  = blockIdx.x;
    const int ctile = bx & 3, sblk = (bx >> 2) & 7, b = bx >> 5;

    for (int q = tid; q < 900; q += 256) {
        int m = q / 225, r = q % 225;
        int o_ = r / 15, i4 = (r % 15) * 4;
        float4 v = *(const float4*)(map_w + m * 900 + o_ * 60 + i4);
        smw[(i4 + 0) * 60 + o_ * 4 + m] = v.x;
        smw[(i4 + 1) * 60 + o_ * 4 + m] = v.y;
        smw[(i4 + 2) * 60 + o_ * 4 + m] = v.z;
        smw[(i4 + 3) * 60 + o_ * 4 + m] = v.w;
    }
    __syncthreads();

    const int c = ctile * 256 + tid;
    if (c >= CC) return;
    const int s0 = sblk * 6;

    const float* sp = g_stat + (size_t)b * 6 * CPAD + c;
    const float gx = sp[0],        gy = sp[CPAD];
    const float gz = sp[2 * CPAD], gw_ = sp[3 * CPAD];
    const float mean = sp[4 * CPAD], sd = sp[5 * CPAD];

    float acc[NOUTV][6];
    float rw[NOUTV];
    #pragma unroll
    for (int o = 0; o < NOUTV; o++) {
        rw[o] = 0.f;
        #pragma unroll
        for (int s = 0; s < 6; s++) acc[o][s] = 0.f;
    }

    const float* xb = x + (size_t)b * LL * CC + c;
    #pragma unroll 2
    for (int i = 0; i < NINV; i++) {
        float xv[6];
        const float* xr = xb + (size_t)(i * SEGS + s0) * CC;
        #pragma unroll
        for (int s = 0; s < 6; s++) xv[s] = __ldg(xr + (size_t)s * CC);
        const float* mwp = smw + i * 60;
        #pragma unroll
        for (int o = 0; o < NOUTV; o++) {
            float4 mw = *(const float4*)(mwp + o * 4);
            float w = gx * mw.x;
            w = fmaf(gy, mw.y, w);
            w = fmaf(gz, mw.z, w);
            w = fmaf(gw_, mw.w, w);
            rw[o] += w;
            #pragma unroll
            for (int s = 0; s < 6; s++)
                acc[o][s] = fmaf(w, xv[s], acc[o][s]);
        }
    }

    float* ob = out + (size_t)b * PREDP * CC + c;
    #pragma unroll
    for (int o = 0; o < NOUTV; o++) {
        float be = gx * __ldg(map_b + o)
                 + gy * __ldg(map_b + NOUTV + o)
                 + gz * __ldg(map_b + 2 * NOUTV + o)
                 + gw_ * __ldg(map_b + 3 * NOUTV + o);
        float bf = be * sd + mean * (1.f - rw[o]);
        #pragma unroll
        for (int s = 0; s < 6; s++)
            ob[(size_t)(o * SEGS + s0 + s) * CC] = acc[o][s] + bf;
    }
}

extern "C" void kernel_launch(void* const* d_in, const int* in_sizes, int n_in,
                              void* d_out, int out_size)
{
    const float* x      = (const float*)d_in[0];
    const float* conv_w = (const float*)d_in[1];
    const float* conv_b = (const float*)d_in[2];
    const float* gate_w = (const float*)d_in[3];
    const float* gate_b = (const float*)d_in[4];
    const float* map_w  = (const float*)d_in[5];
    const float* map_b  = (const float*)d_in[6];
    float* out = (float*)d_out;

    kA_stats_conv<<<BB * NCHUNK * 4, 256>>>(x, conv_w, gate_w);
    kB_gates<<<BB * 4, 256>>>(conv_w, conv_b, gate_w, gate_b);
    kC_map<<<BB * 8 * 4, 256>>>(x, map_w, map_b, out);
}